// round 5
// baseline (speedup 1.0000x reference)
#include <cuda_runtime.h>
#include <cuda_bf16.h>
#include <cstdint>

// Problem constants (fixed by the dataset).
#define TREES 64
#define DNODES 255      // internal nodes per tree (2^8 - 1)
#define KLEAF 256       // leaves per tree
#define MFEAT 512       // features
#define CCLS 8          // classes
#define BATCH 4096

// Blocking
#define TT 16           // trees per block (gridDim.y = TREES/TT = 4)
#define BB 32           // batch rows per block
#define WB 8            // batch rows per warp (4 warps/block)

// Scratch (no cudaMalloc allowed): packed per-node parameters.
// g_node[t*DNODES+d] = { __int_as_float(feature_index), 5*b1 }.
__device__ float2 g_node[TREES * DNODES];

// ---------------------------------------------------------------------------
// Preprocess: extract one-hot feature index from W1 rows; pack with 5*b1.
// One warp per (t,d) row of 512 floats.
// ---------------------------------------------------------------------------
__global__ void prep_kernel(const float* __restrict__ W1,
                            const float* __restrict__ b1)
{
    int row = blockIdx.x * (blockDim.x >> 5) + (threadIdx.x >> 5);
    if (row >= TREES * DNODES) return;
    int lane = threadIdx.x & 31;

    const float4* w4 = reinterpret_cast<const float4*>(W1 + (size_t)row * MFEAT);
    int idx = 0;
#pragma unroll
    for (int i = 0; i < 4; i++) {
        float4 v = w4[i * 32 + lane];
        int base = (i * 32 + lane) * 4;
        if (v.x != 0.0f) idx = base + 0;
        if (v.y != 0.0f) idx = base + 1;
        if (v.z != 0.0f) idx = base + 2;
        if (v.w != 0.0f) idx = base + 3;
    }
#pragma unroll
    for (int off = 16; off; off >>= 1)
        idx = max(idx, __shfl_xor_sync(0xffffffffu, idx, off));
    if (lane == 0) {
        // sigmoid(10x+10b) = 0.5 + 0.5*tanh(5x+5b)
        g_node[row] = make_float2(__int_as_float(idx), 5.0f * b1[row]);
    }
}

// th = tanh(z) via single MUFU.TANH.
__device__ __forceinline__ float tanhf_hw(float z)
{
    float r;
    asm("tanh.approx.f32 %0, %1;" : "=f"(r) : "f"(z));
    return r;
}

// Pack two floats into a 64-bit register pair.
__device__ __forceinline__ unsigned long long pk2(float lo, float hi)
{
    unsigned long long r;
    asm("mov.b64 %0, {%1, %2};" : "=l"(r) : "f"(lo), "f"(hi));
    return r;
}
// Packed dual FFMA (Blackwell FFMA2, PTX-only).
__device__ __forceinline__ unsigned long long ffma2(unsigned long long a,
                                                    unsigned long long b,
                                                    unsigned long long c)
{
    unsigned long long d;
    asm("fma.rn.f32x2 %0, %1, %2, %3;" : "=l"(d) : "l"(a), "l"(b), "l"(c));
    return d;
}
__device__ __forceinline__ void upk2(unsigned long long v, float& lo, float& hi)
{
    asm("mov.b64 {%0, %1}, %2;" : "=f"(lo), "=f"(hi) : "l"(v));
}

// ---------------------------------------------------------------------------
// Main kernel. Block: 128 threads = 4 warps; covers BB=32 batch rows x TT=16
// trees. Warp w owns batch rows [8w, 8w+8). Lane owns the leaf subtree
// k in [8*lane, 8*lane+8) -> Cw[t] loads straight into 32 f32x2 registers
// (coalesced LDG.128; lane region is 64 contiguous floats). Node params load
// straight into registers from the packed L2-resident g_node table. After the
// initial x staging there are NO block barriers: warps run fully independent,
// so per-tree L2 latency is one MLP-16 window and execution-unit bursts from
// different warps desynchronize.
// Prefix levels 0..4 (nodes 0..30) exchanged via 5 independent shfls:
//   n_l = 2^l - 1 + (lane >> (5-l)).
// ---------------------------------------------------------------------------
__global__ __launch_bounds__(128, 3)
void forest_kernel(const float* __restrict__ x,
                   const float* __restrict__ Cw,
                   float* __restrict__ out)
{
    extern __shared__ float smem[];
    float* xs = smem;                               // 32*512 floats (64 KB)

    const int tid   = threadIdx.x;
    const int lane  = tid & 31;
    const int warp  = tid >> 5;
    const int bbase = blockIdx.x * BB;
    const int tbase = blockIdx.y * TT;

    // Stage 32 x-rows (64 KB) cooperatively, coalesced float4.
    {
        const float4* x4  = reinterpret_cast<const float4*>(x + (size_t)bbase * MFEAT);
        float4*       xs4 = reinterpret_cast<float4*>(xs);
#pragma unroll
        for (int i = 0; i < 32; i++)
            xs4[i * 128 + tid] = x4[i * 128 + tid];
    }

    // Tree-independent per-lane prefix constants.
    const int pn = (lane < 31) ? lane : 0;        // node this lane evaluates
    const int n1 = 1  + (lane >> 4);
    const int n2 = 3  + (lane >> 3);
    const int n3 = 7  + (lane >> 2);
    const int n4 = 15 + (lane >> 1);
    const float sg0 = (lane & 16) ? 0.5f : -0.5f; // level-l factor = 0.5 + sg*th
    const float sg1 = (lane & 8)  ? 0.5f : -0.5f;
    const float sg2 = (lane & 4)  ? 0.5f : -0.5f;
    const float sg3 = (lane & 2)  ? 0.5f : -0.5f;
    const float sg4 = (lane & 1)  ? 0.5f : -0.5f;

    unsigned long long acc2[WB][4];
#pragma unroll
    for (int b = 0; b < WB; b++)
#pragma unroll
        for (int q = 0; q < 4; q++) acc2[b][q] = 0ull;

    const float* xw = xs + warp * WB * MFEAT;     // this warp's 8 rows

    __syncthreads();                               // xs ready (only barrier)

#pragma unroll 1
    for (int tt = 0; tt < TT; tt++) {
        const int t = tbase + tt;

        // Per-lane node parameters: direct L2-resident loads (no smem).
        const float2* nd = g_node + t * DNODES;
        const float2 npre = nd[pn];
        const float2 nl5  = nd[31 + lane];
        const float2 n6a  = nd[63 + 2 * lane];
        const float2 n6b  = nd[64 + 2 * lane];
        const float2 n70  = nd[127 + 4 * lane];
        const float2 n71  = nd[128 + 4 * lane];
        const float2 n72  = nd[129 + 4 * lane];
        const float2 n73  = nd[130 + 4 * lane];
        const int fpre = __float_as_int(npre.x);
        const int f5   = __float_as_int(nl5.x);
        const int f6a  = __float_as_int(n6a.x);
        const int f6b  = __float_as_int(n6b.x);
        const int f70  = __float_as_int(n70.x);
        const int f71  = __float_as_int(n71.x);
        const int f72  = __float_as_int(n72.x);
        const int f73  = __float_as_int(n73.x);

        // Cw for this lane's 8 leaves: 64 contiguous floats -> 8 x LDG.128,
        // landing directly as packed f32x2 operands.
        unsigned long long cwr2[8][4];
        {
            const ulonglong2* cw2 = reinterpret_cast<const ulonglong2*>(
                Cw + (size_t)t * (KLEAF * CCLS) + lane * 64);
#pragma unroll
            for (int j = 0; j < 8; j++) {
                ulonglong2 a = cw2[j * 2];       // classes 0..3
                ulonglong2 c = cw2[j * 2 + 1];   // classes 4..7
                cwr2[j][0] = a.x;  cwr2[j][1] = a.y;
                cwr2[j][2] = c.x;  cwr2[j][3] = c.y;
            }
        }

#pragma unroll 1
        for (int b = 0; b < WB; b++) {
            const float* xr = xw + b * MFEAT;

            // thp first so the 5 shfls can issue early.
            float thp  = tanhf_hw(fmaf(5.0f, xr[fpre], npre.y));
            float u0 = __shfl_sync(0xffffffffu, thp, 0);
            float u1 = __shfl_sync(0xffffffffu, thp, n1);
            float u2 = __shfl_sync(0xffffffffu, thp, n2);
            float u3 = __shfl_sync(0xffffffffu, thp, n3);
            float u4 = __shfl_sync(0xffffffffu, thp, n4);

            float th5  = tanhf_hw(fmaf(5.0f, xr[f5],  nl5.y));
            float th6a = tanhf_hw(fmaf(5.0f, xr[f6a], n6a.y));
            float th6b = tanhf_hw(fmaf(5.0f, xr[f6b], n6b.y));
            float th70 = tanhf_hw(fmaf(5.0f, xr[f70], n70.y));
            float th71 = tanhf_hw(fmaf(5.0f, xr[f71], n71.y));
            float th72 = tanhf_hw(fmaf(5.0f, xr[f72], n72.y));
            float th73 = tanhf_hw(fmaf(5.0f, xr[f73], n73.y));

            // Prefix product over levels 0..4.
            float g0 = fmaf(sg0, u0, 0.5f);
            float g1 = fmaf(sg1, u1, 0.5f);
            float g2 = fmaf(sg2, u2, 0.5f);
            float g3 = fmaf(sg3, u3, 0.5f);
            float g4 = fmaf(sg4, u4, 0.5f);
            float p = (g0 * g1) * (g2 * g3) * g4;

            // Subtree expansion (levels 5..7) -> 8 leaf probabilities.
            float f5n = fmaf(-0.5f, th5, 0.5f),  f5p = fmaf(0.5f, th5, 0.5f);
            float pA = p * f5n, pB = p * f5p;
            float a6n = fmaf(-0.5f, th6a, 0.5f), a6p = fmaf(0.5f, th6a, 0.5f);
            float b6n = fmaf(-0.5f, th6b, 0.5f), b6p = fmaf(0.5f, th6b, 0.5f);
            float p00 = pA * a6n, p01 = pA * a6p;
            float p10 = pB * b6n, p11 = pB * b6p;
            float c0n = fmaf(-0.5f, th70, 0.5f), c0p = fmaf(0.5f, th70, 0.5f);
            float c1n = fmaf(-0.5f, th71, 0.5f), c1p = fmaf(0.5f, th71, 0.5f);
            float c2n = fmaf(-0.5f, th72, 0.5f), c2p = fmaf(0.5f, th72, 0.5f);
            float c3n = fmaf(-0.5f, th73, 0.5f), c3p = fmaf(0.5f, th73, 0.5f);
            float P[8];
            P[0] = p00 * c0n;  P[1] = p00 * c0p;
            P[2] = p01 * c1n;  P[3] = p01 * c1p;
            P[4] = p10 * c2n;  P[5] = p10 * c2p;
            P[6] = p11 * c3n;  P[7] = p11 * c3p;

            // Contraction with register-resident Cw: 32 FFMA2 (4 indep chains).
#pragma unroll
            for (int j = 0; j < 8; j++) {
                unsigned long long pp = pk2(P[j], P[j]);
#pragma unroll
                for (int q = 0; q < 4; q++)
                    acc2[b][q] = ffma2(pp, cwr2[j][q], acc2[b][q]);
            }
        }
    }

    // Unpack, cross-lane reduce (leaves were split over lanes), write out.
    const float inv_t = 1.0f / (float)TREES;
#pragma unroll
    for (int b = 0; b < WB; b++) {
        float acc[CCLS];
#pragma unroll
        for (int q = 0; q < 4; q++)
            upk2(acc2[b][q], acc[2 * q], acc[2 * q + 1]);
#pragma unroll
        for (int c = 0; c < CCLS; c++) {
            float v = acc[c];
#pragma unroll
            for (int off = 16; off; off >>= 1)
                v += __shfl_xor_sync(0xffffffffu, v, off);
            acc[c] = v;
        }
        if (lane < CCLS) {
            int brow = bbase + warp * WB + b;
            atomicAdd(&out[brow * CCLS + lane], acc[lane] * inv_t);
        }
    }
}

// ---------------------------------------------------------------------------
extern "C" void kernel_launch(void* const* d_in, const int* in_sizes, int n_in,
                              void* d_out, int out_size)
{
    // Identify inputs by element count (order per metadata: input, W1, b1,
    // Bpos, Bneg, Cw — Bpos/Bneg are structurally fixed and unused).
    const float* x  = nullptr;
    const float* W1 = nullptr;
    const float* b1 = nullptr;
    const float* Cw = nullptr;
    for (int i = 0; i < n_in; i++) {
        switch (in_sizes[i]) {
            case BATCH * MFEAT:          x  = (const float*)d_in[i]; break; // 2097152
            case TREES * DNODES * MFEAT: W1 = (const float*)d_in[i]; break; // 8355840
            case TREES * DNODES:         b1 = (const float*)d_in[i]; break; // 16320
            case TREES * KLEAF * CCLS:   Cw = (const float*)d_in[i]; break; // 131072
            default: break;                                                 // Bpos/Bneg
        }
    }
    float* out = (float*)d_out;

    static const size_t smem_bytes = (size_t)(BB * 512) * 4;   // 64 KB
    cudaFuncSetAttribute(forest_kernel,
                         cudaFuncAttributeMaxDynamicSharedMemorySize,
                         (int)smem_bytes);

    cudaMemsetAsync(d_out, 0, (size_t)out_size * sizeof(float), 0);

    {
        int rows = TREES * DNODES;
        int warps_per_block = 8;
        int blocks = (rows + warps_per_block - 1) / warps_per_block;
        prep_kernel<<<blocks, warps_per_block * 32>>>(W1, b1);
    }

    dim3 grid(BATCH / BB, TREES / TT);
    forest_kernel<<<grid, 128, smem_bytes>>>(x, Cw, out);
}

// round 6
// speedup vs baseline: 1.1960x; 1.1960x over previous
#include <cuda_runtime.h>
#include <cuda_bf16.h>
#include <cstdint>

// Problem constants (fixed by the dataset).
#define TREES 64
#define DNODES 255      // internal nodes per tree (2^8 - 1)
#define KLEAF 256       // leaves per tree
#define MFEAT 512       // features
#define CCLS 8          // classes
#define BATCH 4096

// Blocking: smaller tiles for occupancy (5 CTAs/SM = 20 warps, vs 3/12 before).
#define TT 8            // trees per block (gridDim.y = TREES/TT = 8)
#define BB 16           // batch rows per block
#define WB 4            // batch rows per warp (4 warps/block)

// Scratch (no cudaMalloc allowed): packed per-node parameters.
// g_node[t*DNODES+d] = { __int_as_float(feature_index), 5*b1 }.
__device__ float2 g_node[TREES * DNODES];

// ---------------------------------------------------------------------------
// Preprocess: extract one-hot feature index from W1 rows; pack with 5*b1.
// One warp per (t,d) row of 512 floats.
// ---------------------------------------------------------------------------
__global__ void prep_kernel(const float* __restrict__ W1,
                            const float* __restrict__ b1)
{
    int row = blockIdx.x * (blockDim.x >> 5) + (threadIdx.x >> 5);
    if (row >= TREES * DNODES) return;
    int lane = threadIdx.x & 31;

    const float4* w4 = reinterpret_cast<const float4*>(W1 + (size_t)row * MFEAT);
    int idx = 0;
#pragma unroll
    for (int i = 0; i < 4; i++) {
        float4 v = w4[i * 32 + lane];
        int base = (i * 32 + lane) * 4;
        if (v.x != 0.0f) idx = base + 0;
        if (v.y != 0.0f) idx = base + 1;
        if (v.z != 0.0f) idx = base + 2;
        if (v.w != 0.0f) idx = base + 3;
    }
#pragma unroll
    for (int off = 16; off; off >>= 1)
        idx = max(idx, __shfl_xor_sync(0xffffffffu, idx, off));
    if (lane == 0) {
        // sigmoid(10x+10b) = 0.5 + 0.5*tanh(5x+5b)
        g_node[row] = make_float2(__int_as_float(idx), 5.0f * b1[row]);
    }
}

// th = tanh(z) via single MUFU.TANH.
__device__ __forceinline__ float tanhf_hw(float z)
{
    float r;
    asm("tanh.approx.f32 %0, %1;" : "=f"(r) : "f"(z));
    return r;
}

// Pack two floats into a 64-bit register pair.
__device__ __forceinline__ unsigned long long pk2(float lo, float hi)
{
    unsigned long long r;
    asm("mov.b64 %0, {%1, %2};" : "=l"(r) : "f"(lo), "f"(hi));
    return r;
}
// Packed dual FFMA (Blackwell FFMA2, PTX-only).
__device__ __forceinline__ unsigned long long ffma2(unsigned long long a,
                                                    unsigned long long b,
                                                    unsigned long long c)
{
    unsigned long long d;
    asm("fma.rn.f32x2 %0, %1, %2, %3;" : "=l"(d) : "l"(a), "l"(b), "l"(c));
    return d;
}
__device__ __forceinline__ void upk2(unsigned long long v, float& lo, float& hi)
{
    asm("mov.b64 {%0, %1}, %2;" : "=f"(lo), "=f"(hi) : "l"(v));
}

// ---------------------------------------------------------------------------
// Main kernel. Block: 128 threads = 4 warps; covers BB=16 batch rows x TT=8
// trees. Warp w owns batch rows [4w, 4w+4). Lane owns the leaf subtree
// k in [8*lane, 8*lane+8) -> Cw[t] lives in 32 x f32x2 registers per lane,
// unpacked from a block-shared swizzled smem stage (Cw read ONCE per block
// per tree from L2). Node tables staged in smem per tree. Prefix levels 0..4
// (nodes 0..30) exchanged via 5 independent shfls:
//   n_l = 2^l - 1 + (lane >> (5-l)).
// Smem total ~43 KB -> 5 CTAs/SM = 20 resident warps (latency hiding), vs 12
// in the previous 74 KB configuration.
// ---------------------------------------------------------------------------
__global__ __launch_bounds__(128, 5)
void forest_kernel(const float* __restrict__ x,
                   const float* __restrict__ Cw,
                   float* __restrict__ out)
{
    extern __shared__ float smem[];
    float*  xs    = smem;                                       // 16*512 floats (32 KB)
    float4* cwsh4 = reinterpret_cast<float4*>(smem + BB * 512); // 512 float4 (8 KB)
    int*    ftsh  = reinterpret_cast<int*>(smem + BB * 512 + 2048);   // 256 ints
    float*  tbsh  = reinterpret_cast<float*>(ftsh + 256);             // 256 floats

    const int tid   = threadIdx.x;
    const int lane  = tid & 31;
    const int warp  = tid >> 5;
    const int bbase = blockIdx.x * BB;
    const int tbase = blockIdx.y * TT;

    // Stage 16 x-rows (32 KB) cooperatively, coalesced float4.
    {
        const float4* x4  = reinterpret_cast<const float4*>(x + (size_t)bbase * MFEAT);
        float4*       xs4 = reinterpret_cast<float4*>(xs);
#pragma unroll
        for (int i = 0; i < 16; i++)
            xs4[i * 128 + tid] = x4[i * 128 + tid];
    }

    // Tree-independent per-lane prefix constants.
    const int pn = (lane < 31) ? lane : 0;        // node this lane evaluates
    const int n1 = 1  + (lane >> 4);
    const int n2 = 3  + (lane >> 3);
    const int n3 = 7  + (lane >> 2);
    const int n4 = 15 + (lane >> 1);
    const float sg0 = (lane & 16) ? 0.5f : -0.5f; // level-l factor = 0.5 + sg*th
    const float sg1 = (lane & 8)  ? 0.5f : -0.5f;
    const float sg2 = (lane & 4)  ? 0.5f : -0.5f;
    const float sg3 = (lane & 2)  ? 0.5f : -0.5f;
    const float sg4 = (lane & 1)  ? 0.5f : -0.5f;

    unsigned long long acc2[WB][4];
#pragma unroll
    for (int b = 0; b < WB; b++)
#pragma unroll
        for (int q = 0; q < 4; q++) acc2[b][q] = 0ull;

    const float* xw = xs + warp * WB * MFEAT;     // this warp's 4 rows

    for (int tt = 0; tt < TT; tt++) {
        const int t = tbase + tt;
        __syncthreads();   // xs ready / previous iteration's shared reads done

        // Stage per-tree node tables (packed float2 -> split arrays).
        for (int i = tid; i < DNODES; i += 128) {
            float2 v = g_node[t * DNODES + i];
            ftsh[i] = __float_as_int(v.x);
            tbsh[i] = v.y;
        }
        // Stage Cw[t] (2048 floats) XOR-swizzled so per-lane LDS.128 is
        // bank-conflict-free.
        {
            const float4* cw4 = reinterpret_cast<const float4*>(Cw + (size_t)t * KLEAF * CCLS);
#pragma unroll
            for (int q = tid; q < 512; q += 128)
                cwsh4[q ^ ((q >> 4) & 7)] = cw4[q];
        }
        __syncthreads();

        // Per-lane packed Cw copy for its 8 leaves (32 x f32x2 = 64 regs).
        unsigned long long cwr2[8][4];
#pragma unroll
        for (int j = 0; j < 8; j++) {
            int k = lane * 8 + j;
#pragma unroll
            for (int h = 0; h < 2; h++) {
                int p4 = (k * 2 + h) ^ (lane & 7);
                float4 v = cwsh4[p4];
                cwr2[j][2 * h + 0] = pk2(v.x, v.y);
                cwr2[j][2 * h + 1] = pk2(v.z, v.w);
            }
        }

        // Per-lane node parameters.
        const int   fpre = ftsh[pn];             const float tpre = tbsh[pn];
        const int   f5   = ftsh[31 + lane];      const float t5   = tbsh[31 + lane];
        const int   f6a  = ftsh[63 + 2 * lane];  const float t6a  = tbsh[63 + 2 * lane];
        const int   f6b  = ftsh[64 + 2 * lane];  const float t6b  = tbsh[64 + 2 * lane];
        const int   f70  = ftsh[127 + 4 * lane]; const float t70  = tbsh[127 + 4 * lane];
        const int   f71  = ftsh[128 + 4 * lane]; const float t71  = tbsh[128 + 4 * lane];
        const int   f72  = ftsh[129 + 4 * lane]; const float t72  = tbsh[129 + 4 * lane];
        const int   f73  = ftsh[130 + 4 * lane]; const float t73  = tbsh[130 + 4 * lane];

#pragma unroll 1
        for (int b = 0; b < WB; b++) {
            const float* xr = xw + b * MFEAT;

            // thp first so the 5 shfls can issue early.
            float thp  = tanhf_hw(fmaf(5.0f, xr[fpre], tpre));
            float u0 = __shfl_sync(0xffffffffu, thp, 0);
            float u1 = __shfl_sync(0xffffffffu, thp, n1);
            float u2 = __shfl_sync(0xffffffffu, thp, n2);
            float u3 = __shfl_sync(0xffffffffu, thp, n3);
            float u4 = __shfl_sync(0xffffffffu, thp, n4);

            float th5  = tanhf_hw(fmaf(5.0f, xr[f5],  t5));
            float th6a = tanhf_hw(fmaf(5.0f, xr[f6a], t6a));
            float th6b = tanhf_hw(fmaf(5.0f, xr[f6b], t6b));
            float th70 = tanhf_hw(fmaf(5.0f, xr[f70], t70));
            float th71 = tanhf_hw(fmaf(5.0f, xr[f71], t71));
            float th72 = tanhf_hw(fmaf(5.0f, xr[f72], t72));
            float th73 = tanhf_hw(fmaf(5.0f, xr[f73], t73));

            // Prefix product over levels 0..4.
            float g0 = fmaf(sg0, u0, 0.5f);
            float g1 = fmaf(sg1, u1, 0.5f);
            float g2 = fmaf(sg2, u2, 0.5f);
            float g3 = fmaf(sg3, u3, 0.5f);
            float g4 = fmaf(sg4, u4, 0.5f);
            float p = (g0 * g1) * (g2 * g3) * g4;

            // Subtree expansion (levels 5..7) -> 8 leaf probabilities.
            float f5n = fmaf(-0.5f, th5, 0.5f),  f5p = fmaf(0.5f, th5, 0.5f);
            float pA = p * f5n, pB = p * f5p;
            float a6n = fmaf(-0.5f, th6a, 0.5f), a6p = fmaf(0.5f, th6a, 0.5f);
            float b6n = fmaf(-0.5f, th6b, 0.5f), b6p = fmaf(0.5f, th6b, 0.5f);
            float p00 = pA * a6n, p01 = pA * a6p;
            float p10 = pB * b6n, p11 = pB * b6p;
            float c0n = fmaf(-0.5f, th70, 0.5f), c0p = fmaf(0.5f, th70, 0.5f);
            float c1n = fmaf(-0.5f, th71, 0.5f), c1p = fmaf(0.5f, th71, 0.5f);
            float c2n = fmaf(-0.5f, th72, 0.5f), c2p = fmaf(0.5f, th72, 0.5f);
            float c3n = fmaf(-0.5f, th73, 0.5f), c3p = fmaf(0.5f, th73, 0.5f);
            float P[8];
            P[0] = p00 * c0n;  P[1] = p00 * c0p;
            P[2] = p01 * c1n;  P[3] = p01 * c1p;
            P[4] = p10 * c2n;  P[5] = p10 * c2p;
            P[6] = p11 * c3n;  P[7] = p11 * c3p;

            // Contraction with register-resident Cw: 32 FFMA2 (4 indep chains).
#pragma unroll
            for (int j = 0; j < 8; j++) {
                unsigned long long pp = pk2(P[j], P[j]);
#pragma unroll
                for (int q = 0; q < 4; q++)
                    acc2[b][q] = ffma2(pp, cwr2[j][q], acc2[b][q]);
            }
        }
    }

    // Unpack, cross-lane reduce (leaves were split over lanes), write out.
    const float inv_t = 1.0f / (float)TREES;
#pragma unroll
    for (int b = 0; b < WB; b++) {
        float acc[CCLS];
#pragma unroll
        for (int q = 0; q < 4; q++)
            upk2(acc2[b][q], acc[2 * q], acc[2 * q + 1]);
#pragma unroll
        for (int c = 0; c < CCLS; c++) {
            float v = acc[c];
#pragma unroll
            for (int off = 16; off; off >>= 1)
                v += __shfl_xor_sync(0xffffffffu, v, off);
            acc[c] = v;
        }
        if (lane < CCLS) {
            int brow = bbase + warp * WB + b;
            atomicAdd(&out[brow * CCLS + lane], acc[lane] * inv_t);
        }
    }
}

// ---------------------------------------------------------------------------
extern "C" void kernel_launch(void* const* d_in, const int* in_sizes, int n_in,
                              void* d_out, int out_size)
{
    // Identify inputs by element count (order per metadata: input, W1, b1,
    // Bpos, Bneg, Cw — Bpos/Bneg are structurally fixed and unused).
    const float* x  = nullptr;
    const float* W1 = nullptr;
    const float* b1 = nullptr;
    const float* Cw = nullptr;
    for (int i = 0; i < n_in; i++) {
        switch (in_sizes[i]) {
            case BATCH * MFEAT:          x  = (const float*)d_in[i]; break; // 2097152
            case TREES * DNODES * MFEAT: W1 = (const float*)d_in[i]; break; // 8355840
            case TREES * DNODES:         b1 = (const float*)d_in[i]; break; // 16320
            case TREES * KLEAF * CCLS:   Cw = (const float*)d_in[i]; break; // 131072
            default: break;                                                 // Bpos/Bneg
        }
    }
    float* out = (float*)d_out;

    static const size_t smem_bytes =
        (size_t)(BB * 512 + 2048 + 256 + 256) * 4;   // ~43 KB
    cudaFuncSetAttribute(forest_kernel,
                         cudaFuncAttributeMaxDynamicSharedMemorySize,
                         (int)smem_bytes);

    cudaMemsetAsync(d_out, 0, (size_t)out_size * sizeof(float), 0);

    {
        int rows = TREES * DNODES;
        int warps_per_block = 8;
        int blocks = (rows + warps_per_block - 1) / warps_per_block;
        prep_kernel<<<blocks, warps_per_block * 32>>>(W1, b1);
    }

    dim3 grid(BATCH / BB, TREES / TT);
    forest_kernel<<<grid, 128, smem_bytes>>>(x, Cw, out);
}

// round 7
// speedup vs baseline: 2.1849x; 1.8269x over previous
#include <cuda_runtime.h>
#include <cuda_bf16.h>
#include <cstdint>

// Problem constants (fixed by the dataset).
#define TREES 64
#define DNODES 255      // internal nodes per tree (2^8 - 1)
#define KLEAF 256       // leaves per tree
#define MFEAT 512       // features
#define CCLS 8          // classes
#define BATCH 4096

// Blocking: lane = batch row. CTA = 256 threads (8 warps) x 32 rows.
// Warp w owns leaves [32w, 32w+32) of each tree; CTA covers TGROUP trees.
#define ROWS 32
#define TGROUP 32       // trees per CTA (gridDim.y = TREES/TGROUP = 2)
#define XSTRIDE 513     // padded row stride: bank(lane*513+f) = (lane+f)%32 -> conflict-free

// Scratch (no cudaMalloc allowed): packed per-node parameters.
// g_node[t*DNODES+d] = { __int_as_float(feature_index), 5*b1 }.
__device__ float2 g_node[TREES * DNODES];

// ---------------------------------------------------------------------------
// Preprocess: extract one-hot feature index from W1 rows; pack with 5*b1.
// One warp per (t,d) row of 512 floats.
// ---------------------------------------------------------------------------
__global__ void prep_kernel(const float* __restrict__ W1,
                            const float* __restrict__ b1)
{
    int row = blockIdx.x * (blockDim.x >> 5) + (threadIdx.x >> 5);
    if (row >= TREES * DNODES) return;
    int lane = threadIdx.x & 31;

    const float4* w4 = reinterpret_cast<const float4*>(W1 + (size_t)row * MFEAT);
    int idx = 0;
#pragma unroll
    for (int i = 0; i < 4; i++) {
        float4 v = w4[i * 32 + lane];
        int base = (i * 32 + lane) * 4;
        if (v.x != 0.0f) idx = base + 0;
        if (v.y != 0.0f) idx = base + 1;
        if (v.z != 0.0f) idx = base + 2;
        if (v.w != 0.0f) idx = base + 3;
    }
#pragma unroll
    for (int off = 16; off; off >>= 1)
        idx = max(idx, __shfl_xor_sync(0xffffffffu, idx, off));
    if (lane == 0) {
        // sigmoid(10x+10b) = 0.5 + 0.5*tanh(5x+5b)
        g_node[row] = make_float2(__int_as_float(idx), 5.0f * b1[row]);
    }
}

// th = tanh(z) via single MUFU.TANH.
__device__ __forceinline__ float tanhf_hw(float z)
{
    float r;
    asm("tanh.approx.f32 %0, %1;" : "=f"(r) : "f"(z));
    return r;
}

// Pack two floats into a 64-bit register pair.
__device__ __forceinline__ unsigned long long pk2(float lo, float hi)
{
    unsigned long long r;
    asm("mov.b64 %0, {%1, %2};" : "=l"(r) : "f"(lo), "f"(hi));
    return r;
}
// Packed dual FFMA (Blackwell FFMA2, PTX-only).
__device__ __forceinline__ unsigned long long ffma2(unsigned long long a,
                                                    unsigned long long b,
                                                    unsigned long long c)
{
    unsigned long long d;
    asm("fma.rn.f32x2 %0, %1, %2, %3;" : "=l"(d) : "l"(a), "l"(b), "l"(c));
    return d;
}
__device__ __forceinline__ void upk2(unsigned long long v, float& lo, float& hi)
{
    asm("mov.b64 {%0, %1}, %2;" : "=f"(lo), "=f"(hi) : "l"(v));
}

// ---------------------------------------------------------------------------
// Main kernel, row-per-lane layout:
//  - lane owns batch row (bbase+lane): x gathers hit xs[lane*513+f], banks
//    (lane+f)%32 -> conflict-free; node params / Cw are warp-uniform LDS
//    broadcasts (1 wavefront).
//  - warp w owns leaves [32w,32w+32): path nodes a0..a3 (levels 0..3 with
//    a3 = 7+w) then the 30-node subtree below; 34 tanh per lane-tree.
//  - no shfls, no cross-lane reduction: lane's acc covers its own row.
// ---------------------------------------------------------------------------
__global__ __launch_bounds__(256, 3)
void forest_kernel(const float* __restrict__ x,
                   const float* __restrict__ Cw,
                   float* __restrict__ out)
{
    extern __shared__ float smem[];
    float*  xs   = smem;                                           // 32*513 floats
    float4* cwsh = reinterpret_cast<float4*>(smem + ROWS * XSTRIDE);     // 512 float4 (8 KB)
    float2* ndsh = reinterpret_cast<float2*>(smem + ROWS * XSTRIDE + 2048); // 255 float2

    const int tid   = threadIdx.x;
    const int lane  = tid & 31;
    const int w     = tid >> 5;                  // warp id = leaf slice
    const int bbase = blockIdx.x * ROWS;
    const int tbase = blockIdx.y * TGROUP;

    // Stage 32 x-rows into padded smem (coalesced LDG.128, scalar STS).
    {
        const float4* xg4 = reinterpret_cast<const float4*>(x + (size_t)bbase * MFEAT);
#pragma unroll
        for (int i = 0; i < (ROWS * MFEAT / 4) / 256; i++) {   // 16 iters
            int idx4 = i * 256 + tid;
            float4 v = xg4[idx4];
            int row = idx4 >> 7;              // 128 float4 per row
            int f   = (idx4 & 127) * 4;
            float* d = xs + row * XSTRIDE + f;
            d[0] = v.x; d[1] = v.y; d[2] = v.z; d[3] = v.w;
        }
    }

    // Warp-constant path node ids / signs (levels 0..2), level-3 node = 7+w.
    const float sg0 = (w & 4) ? 0.5f : -0.5f;
    const float sg1 = (w & 2) ? 0.5f : -0.5f;
    const float sg2 = (w & 1) ? 0.5f : -0.5f;
    const int a1 = 1 + (w >> 2);
    const int a2 = 3 + (w >> 1);
    const int a3 = 7 + w;

    const float* xr = xs + lane * XSTRIDE;       // this lane's row

    unsigned long long acc2[4] = {0ull, 0ull, 0ull, 0ull};

#pragma unroll 1
    for (int tt = 0; tt < TGROUP; tt++) {
        const int t = tbase + tt;
        __syncthreads();   // x staged / previous tree's tables no longer read

        // Stage per-tree tables (uniform-broadcast consumers -> no swizzle).
        for (int i = tid; i < DNODES; i += 256)
            ndsh[i] = g_node[t * DNODES + i];
        {
            const float4* cw4 = reinterpret_cast<const float4*>(Cw + (size_t)t * KLEAF * CCLS);
            cwsh[tid]       = cw4[tid];
            cwsh[tid + 256] = cw4[tid + 256];
        }
        __syncthreads();

        // Node evaluator: broadcast LDS of params, conflict-free gather, tanh.
        auto nodeth = [&](int n) -> float {
            float2 nv = ndsh[n];
            return tanhf_hw(fmaf(5.0f, xr[__float_as_int(nv.x)], nv.y));
        };

        // Path levels 0..3.
        float th0 = nodeth(0);
        float th1 = nodeth(a1);
        float th2 = nodeth(a2);
        float th3 = nodeth(a3);
        float pre = fmaf(sg0, th0, 0.5f) * fmaf(sg1, th1, 0.5f) * fmaf(sg2, th2, 0.5f);
        float pA = pre * fmaf(-0.5f, th3, 0.5f);
        float pB = pre * fmaf( 0.5f, th3, 0.5f);

        // Level 4 (2 nodes) -> q[4].
        float q[4];
        {
            float t4a = nodeth(15 + 2 * w);
            float t4b = nodeth(16 + 2 * w);
            q[0] = pA * fmaf(-0.5f, t4a, 0.5f); q[1] = pA * fmaf(0.5f, t4a, 0.5f);
            q[2] = pB * fmaf(-0.5f, t4b, 0.5f); q[3] = pB * fmaf(0.5f, t4b, 0.5f);
        }
        // Level 5 (4 nodes) -> r[8].
        float r[8];
#pragma unroll
        for (int i = 0; i < 4; i++) {
            float th = nodeth(31 + 4 * w + i);
            r[2 * i]     = q[i] * fmaf(-0.5f, th, 0.5f);
            r[2 * i + 1] = q[i] * fmaf( 0.5f, th, 0.5f);
        }
        // Level 6 (8 nodes) -> u[16].
        float u[16];
#pragma unroll
        for (int i = 0; i < 8; i++) {
            float th = nodeth(63 + 8 * w + i);
            u[2 * i]     = r[i] * fmaf(-0.5f, th, 0.5f);
            u[2 * i + 1] = r[i] * fmaf( 0.5f, th, 0.5f);
        }

        // Level 7 (16 nodes): 32 leaves, contract immediately with broadcast Cw.
        const ulonglong2* cwp = reinterpret_cast<const ulonglong2*>(cwsh) + (size_t)w * 64;
#pragma unroll
        for (int i = 0; i < 16; i++) {
            float th = nodeth(127 + 16 * w + i);
            float P0 = u[i] * fmaf(-0.5f, th, 0.5f);
            float P1 = u[i] * fmaf( 0.5f, th, 0.5f);
            // leaf (2i): classes 0..3, 4..7 ; leaf (2i+1) likewise.
            ulonglong2 cA0 = cwp[4 * i + 0];
            ulonglong2 cA1 = cwp[4 * i + 1];
            ulonglong2 cB0 = cwp[4 * i + 2];
            ulonglong2 cB1 = cwp[4 * i + 3];
            unsigned long long pp0 = pk2(P0, P0);
            unsigned long long pp1 = pk2(P1, P1);
            acc2[0] = ffma2(pp0, cA0.x, acc2[0]);
            acc2[1] = ffma2(pp0, cA0.y, acc2[1]);
            acc2[2] = ffma2(pp0, cA1.x, acc2[2]);
            acc2[3] = ffma2(pp0, cA1.y, acc2[3]);
            acc2[0] = ffma2(pp1, cB0.x, acc2[0]);
            acc2[1] = ffma2(pp1, cB0.y, acc2[1]);
            acc2[2] = ffma2(pp1, cB1.x, acc2[2]);
            acc2[3] = ffma2(pp1, cB1.y, acc2[3]);
        }
    }

    // Lane owns row bbase+lane entirely for its leaf slice: just scale and
    // atomically add (8 slices x 2 tree-groups accumulate per output element).
    const float inv_t = 1.0f / (float)TREES;
    float a[CCLS];
#pragma unroll
    for (int qq = 0; qq < 4; qq++)
        upk2(acc2[qq], a[2 * qq], a[2 * qq + 1]);
    float* orow = out + (size_t)(bbase + lane) * CCLS;
#pragma unroll
    for (int c = 0; c < CCLS; c++)
        atomicAdd(&orow[c], a[c] * inv_t);
}

// ---------------------------------------------------------------------------
extern "C" void kernel_launch(void* const* d_in, const int* in_sizes, int n_in,
                              void* d_out, int out_size)
{
    // Identify inputs by element count (order per metadata: input, W1, b1,
    // Bpos, Bneg, Cw — Bpos/Bneg are structurally fixed and unused).
    const float* x  = nullptr;
    const float* W1 = nullptr;
    const float* b1 = nullptr;
    const float* Cw = nullptr;
    for (int i = 0; i < n_in; i++) {
        switch (in_sizes[i]) {
            case BATCH * MFEAT:          x  = (const float*)d_in[i]; break; // 2097152
            case TREES * DNODES * MFEAT: W1 = (const float*)d_in[i]; break; // 8355840
            case TREES * DNODES:         b1 = (const float*)d_in[i]; break; // 16320
            case TREES * KLEAF * CCLS:   Cw = (const float*)d_in[i]; break; // 131072
            default: break;                                                 // Bpos/Bneg
        }
    }
    float* out = (float*)d_out;

    static const size_t smem_bytes =
        (size_t)(ROWS * XSTRIDE + 2048 + 512) * 4;   // ~75.9 KB
    cudaFuncSetAttribute(forest_kernel,
                         cudaFuncAttributeMaxDynamicSharedMemorySize,
                         (int)smem_bytes);

    cudaMemsetAsync(d_out, 0, (size_t)out_size * sizeof(float), 0);

    {
        int rows = TREES * DNODES;
        int warps_per_block = 8;
        int blocks = (rows + warps_per_block - 1) / warps_per_block;
        prep_kernel<<<blocks, warps_per_block * 32>>>(W1, b1);
    }

    dim3 grid(BATCH / ROWS, TREES / TGROUP);   // (128, 2)
    forest_kernel<<<grid, 256, smem_bytes>>>(x, Cw, out);
}